// round 2
// baseline (speedup 1.0000x reference)
#include <cuda_runtime.h>
#include <math.h>

#define NB 32
#define NS 2048
#define NH 1024
#define NH4 (NH/4)       // 256 float4 per row
#define WPB 64           // warp-chunks per batch
#define ROWS (NS/WPB)    // 32 rows per warp

// ---- scratch (__device__ globals; no runtime allocation allowed) ----
__device__ float g_q[NB * NH];              // 128 KB
__device__ float g_energy[NB * NS];         // 256 KB (raw energies)
__device__ float g_m[NB * WPB];             // per-chunk running max
__device__ float g_z[NB * WPB];             // per-chunk partial sum
__device__ float g_ctx[NB * WPB * NH];      // 8 MB per-chunk context partials

// ============================================================================
// Kernel 1: q[b,o] = bias[o] + sum_i hidden[b,i] * W[o,i]
// grid (16, 4): blockIdx.x = 64-wide o block, blockIdx.y = 8-wide b block.
// W rows live in registers (read once per CTA), hidden tile in SMEM.
// ============================================================================
__global__ __launch_bounds__(256) void qkernel(const float* __restrict__ hidden,
                                               const float* __restrict__ W,
                                               const float* __restrict__ bias) {
    __shared__ float hid_s[8 * NH];          // 32 KB
    const int t = threadIdx.x;
    const int b0 = blockIdx.y * 8;

    const float4* hid4 = (const float4*)(hidden + (size_t)b0 * NH);
    float4* hs4 = (float4*)hid_s;
    #pragma unroll
    for (int k = 0; k < 8; k++) hs4[t + 256 * k] = hid4[t + 256 * k];
    __syncthreads();

    const int w = t >> 5, lane = t & 31;
    const float4* W4 = (const float4*)W;

    for (int oi = 0; oi < 8; oi++) {
        const int o = blockIdx.x * 64 + w * 8 + oi;
        float4 wr[8];
        #pragma unroll
        for (int p = 0; p < 8; p++) wr[p] = W4[(size_t)o * NH4 + lane + 32 * p];

        for (int bl = 0; bl < 8; bl++) {
            float acc = 0.f;
            #pragma unroll
            for (int p = 0; p < 8; p++) {
                float4 h4 = hs4[bl * NH4 + lane + 32 * p];
                acc += wr[p].x * h4.x + wr[p].y * h4.y
                     + wr[p].z * h4.z + wr[p].w * h4.w;
            }
            #pragma unroll
            for (int off = 16; off; off >>= 1)
                acc += __shfl_xor_sync(0xffffffffu, acc, off);
            if (lane == 0) g_q[(size_t)(b0 + bl) * NH + o] = acc + bias[o];
        }
    }
}

// ============================================================================
// Kernel 2: fused single-pass energy + online-softmax context accumulation.
// grid (8, 32): blockIdx.y = b, warp-chunk c = blockIdx.x*8 + warp (0..63).
// Each warp streams 32 enc rows; each row is read from HBM ONCE into
// registers, used for the dot product AND the context accumulate.
// __launch_bounds__(256,2): cap regs at 128 so 2 CTAs/SM stay co-resident
// (grid is 256 CTAs on 148 SMs; the 108 doubled-up SMs must overlap, not
// serialize, to keep chip-wide MLP high).
// ============================================================================
__global__ __launch_bounds__(256, 2) void mainkernel(const float* __restrict__ enc) {
    __shared__ float q_s[NH];                // 4 KB
    const int t = threadIdx.x, w = t >> 5, lane = t & 31;
    const int b = blockIdx.y;

    ((float4*)q_s)[t] = ((const float4*)g_q)[(size_t)b * NH4 + t];
    __syncthreads();

    const int c = blockIdx.x * 8 + w;
    const float4* enc4 = (const float4*)enc
                       + ((size_t)b * NS + (size_t)c * ROWS) * NH4;
    const float4* qs4 = (const float4*)q_s;

    float m = -INFINITY, z = 0.f;
    float4 ctx[8];
    #pragma unroll
    for (int p = 0; p < 8; p++) ctx[p] = make_float4(0.f, 0.f, 0.f, 0.f);

    for (int r = 0; r < ROWS; r++) {
        float4 v[8];
        #pragma unroll
        for (int p = 0; p < 8; p++)
            v[p] = enc4[(size_t)r * NH4 + lane + 32 * p];

        float e = 0.f;
        #pragma unroll
        for (int p = 0; p < 8; p++) {
            float4 q4 = qs4[lane + 32 * p];
            e += v[p].x * q4.x + v[p].y * q4.y + v[p].z * q4.z + v[p].w * q4.w;
        }
        #pragma unroll
        for (int off = 16; off; off >>= 1)
            e += __shfl_xor_sync(0xffffffffu, e, off);

        if (lane == 0) g_energy[(size_t)b * NS + c * ROWS + r] = e;

        const float mn = fmaxf(m, e);
        const float sc = __expf(m - mn);     // 0 on first iter (m = -inf)
        const float wt = __expf(e - mn);
        z = z * sc + wt;
        #pragma unroll
        for (int p = 0; p < 8; p++) {
            ctx[p].x = ctx[p].x * sc + wt * v[p].x;
            ctx[p].y = ctx[p].y * sc + wt * v[p].y;
            ctx[p].z = ctx[p].z * sc + wt * v[p].z;
            ctx[p].w = ctx[p].w * sc + wt * v[p].w;
        }
        m = mn;
    }

    const int idx = b * WPB + c;
    if (lane == 0) { g_m[idx] = m; g_z[idx] = z; }
    float4* out4 = (float4*)g_ctx + (size_t)idx * NH4;
    #pragma unroll
    for (int p = 0; p < 8; p++) out4[lane + 32 * p] = ctx[p];
}

// ============================================================================
// Kernel 3: combine chunk partials -> context. grid 128: b = blk/4,
// h block = (blk%4)*256. Exact: M is the true global max (max of chunk maxes).
// ============================================================================
__global__ __launch_bounds__(256) void ctx_kernel(float* __restrict__ out) {
    __shared__ float ms[WPB], ws[WPB], zw[WPB];
    const int t = threadIdx.x;
    const int b = blockIdx.x >> 2;
    const int h = ((blockIdx.x & 3) << 8) + t;

    if (t < WPB) ms[t] = g_m[b * WPB + t];
    __syncthreads();
    float M = -INFINITY;
    #pragma unroll 8
    for (int cc = 0; cc < WPB; cc++) M = fmaxf(M, ms[cc]);
    if (t < WPB) {
        float e = __expf(ms[t] - M);
        ws[t] = e;
        zw[t] = g_z[b * WPB + t] * e;
    }
    __syncthreads();
    float Zt = 0.f;
    #pragma unroll 8
    for (int cc = 0; cc < WPB; cc++) Zt += zw[cc];

    float acc = 0.f;
    #pragma unroll 4
    for (int cc = 0; cc < WPB; cc++)
        acc += g_ctx[(size_t)(b * WPB + cc) * NH + h] * ws[cc];

    out[(size_t)b * NH + h] = acc / Zt;
}

// ============================================================================
// Kernel 4: attention[b,s] = exp(e - M) / Zt. grid 128: b = blk/4,
// s block = (blk%4)*512, 2 s per thread. Written after context region.
// ============================================================================
__global__ __launch_bounds__(256) void att_kernel(float* __restrict__ out) {
    __shared__ float ms[WPB], zw[WPB];
    const int t = threadIdx.x;
    const int b = blockIdx.x >> 2;
    const int s0 = (blockIdx.x & 3) << 9;

    if (t < WPB) ms[t] = g_m[b * WPB + t];
    __syncthreads();
    float M = -INFINITY;
    #pragma unroll 8
    for (int cc = 0; cc < WPB; cc++) M = fmaxf(M, ms[cc]);
    if (t < WPB) zw[t] = g_z[b * WPB + t] * __expf(ms[t] - M);
    __syncthreads();
    float Zt = 0.f;
    #pragma unroll 8
    for (int cc = 0; cc < WPB; cc++) Zt += zw[cc];
    const float inv = 1.f / Zt;

    #pragma unroll
    for (int k = 0; k < 2; k++) {
        const int s = s0 + t + 256 * k;
        out[(size_t)NB * NH + (size_t)b * NS + s] =
            __expf(g_energy[(size_t)b * NS + s] - M) * inv;
    }
}

// ============================================================================
// Launch: inputs per metadata order: hidden, encoder_outputs, W_weight, W_bias.
// Output: context [32*1024] then attention [32*2048] (tuple order), fp32.
// ============================================================================
extern "C" void kernel_launch(void* const* d_in, const int* in_sizes, int n_in,
                              void* d_out, int out_size) {
    const float* hidden = (const float*)d_in[0];
    const float* enc    = (const float*)d_in[1];
    const float* W      = (const float*)d_in[2];
    const float* bias   = (const float*)d_in[3];
    float* out = (float*)d_out;

    qkernel<<<dim3(16, 4), 256>>>(hidden, W, bias);
    mainkernel<<<dim3(8, 32), 256>>>(enc);
    ctx_kernel<<<128, 256>>>(out);
    att_kernel<<<128, 256>>>(out);
}